// round 13
// baseline (speedup 1.0000x reference)
#include <cuda_runtime.h>
#include <cuda_bf16.h>

// ContrastiveLoss via closed-form separable reduction, ONE fused kernel.
// loss = [(N-1)(Sx+Sy) - 2*dot(colsum_x, colsum_y) + 2*sum_i x_i.y_i] / (2N(N-1))
// Label is unused.
//
// Warp-count probe: 128 blocks x 256 threads (1024 warps total, 4x fewer
// than prior rounds), each thread front-batching 16 LDG.128 (8 float4 per
// tensor, MLP=16). Tests whether the ~10us plateau is warp/launch-machinery
// bound (fewer warps -> faster) or short-burst DRAM-service bound (neutral).
// Two-level last-block election; fixed-order reductions -> deterministic.

#define NBLK 128
#define NTHR 256
#define NTOT (NBLK * NTHR)      // 32768 threads
#define DCOLS 128
#define NWARP (NTHR / 32)       // 8 warps per block
#define NGRP 16                 // election groups
#define GRP_SZ (NBLK / NGRP)    // 8 blocks per group

__device__ float4 g_csx4[NBLK * 32];   // per-block column sums (128 cols)
__device__ float4 g_csy4[NBLK * 32];
__device__ float  g_ssx[NBLK];
__device__ float  g_ssy[NBLK];
__device__ float  g_dxy[NBLK];

struct __align__(128) PadCtr { unsigned int v; unsigned int pad[31]; };
__device__ PadCtr g_grp[NGRP];         // zero-init; last block resets
__device__ PadCtr g_super;

__device__ __forceinline__ float dot4(float4 a, float4 b) {
    return fmaf(a.x, b.x, fmaf(a.y, b.y, fmaf(a.z, b.z, a.w * b.w)));
}
__device__ __forceinline__ float4 f4add(float4 a, float4 b) {
    return make_float4(a.x + b.x, a.y + b.y, a.z + b.z, a.w + b.w);
}
__device__ __forceinline__ float4 ldcg4(const float4* p) {
    return __ldcg(p);                  // L2-only load
}

__global__ void __launch_bounds__(NTHR)
cl_fused_kernel(const float4* __restrict__ f1,
                const float4* __restrict__ f2,
                int total4,          // N * 32 float4 per tensor
                int N,
                float* __restrict__ out)
{
    const int t = threadIdx.x;
    const int b = blockIdx.x;
    const int g = b * NTHR + t;
    const int s = t >> 5;            // warp id 0..7
    const int lane = t & 31;

    // ---- Phase 1: 8 float4 per tensor, 16 loads front-batched (MLP=16) ----
    float4 z = make_float4(0.f, 0.f, 0.f, 0.f);
    float4 x[8], y[8];
    if (total4 == 8 * NTOT) {        // exact fit (N=8192, D=128): no predicates
        #pragma unroll
        for (int k = 0; k < 8; k++) {
            x[k] = f1[g + k * NTOT];
            y[k] = f2[g + k * NTOT];
        }
    } else {
        #pragma unroll
        for (int k = 0; k < 8; k++) {
            x[k] = z; y[k] = z;
            if (g + k * NTOT < total4) {
                x[k] = f1[g + k * NTOT];
                y[k] = f2[g + k * NTOT];
            }
        }
    }

    float4 cx4 = z, cy4 = z;
    float ssx = 0.f, ssy = 0.f, dxy = 0.f;
    #pragma unroll
    for (int k = 0; k < 8; k++) {
        cx4 = f4add(cx4, x[k]);
        cy4 = f4add(cy4, y[k]);
        ssx += dot4(x[k], x[k]);
        ssy += dot4(y[k], y[k]);
        dxy += dot4(x[k], y[k]);
    }

    // ---- Block reduce colsums: sum float4 across the 8 warps per lane ----
    __shared__ float4 shx[NTHR];     // 4 KB, reused by finalize
    __shared__ float4 shy[NTHR];     // 4 KB
    shx[t] = cx4;
    shy[t] = cy4;
    __syncthreads();
    if (t < 32) {
        float4 ax = shx[t], ay = shy[t];
        #pragma unroll
        for (int w = 1; w < NWARP; w++) {
            ax = f4add(ax, shx[w * 32 + t]);
            ay = f4add(ay, shy[w * 32 + t]);
        }
        __stcg(&g_csx4[b * 32 + t], ax);   // L2-only coalesced 512B store
        __stcg(&g_csy4[b * 32 + t], ay);
    }

    // ---- Block reduce the 3 scalars (shuffle tree, fixed order) ----
    {
        float a = ssx, e = ssy, d = dxy;
        #pragma unroll
        for (int o = 16; o; o >>= 1) {
            a += __shfl_down_sync(0xffffffffu, a, o);
            e += __shfl_down_sync(0xffffffffu, e, o);
            d += __shfl_down_sync(0xffffffffu, d, o);
        }
        __shared__ float w0[NWARP], w1[NWARP], w2[NWARP];
        if (lane == 0) { w0[s] = a; w1[s] = e; w2[s] = d; }
        __syncthreads();
        if (s == 0 && lane < NWARP) {
            float a2 = w0[lane], e2 = w1[lane], d2 = w2[lane];
            #pragma unroll
            for (int o = 4; o; o >>= 1) {
                a2 += __shfl_down_sync(0x000000ffu, a2, o);
                e2 += __shfl_down_sync(0x000000ffu, e2, o);
                d2 += __shfl_down_sync(0x000000ffu, d2, o);
            }
            if (lane == 0) { g_ssx[b] = a2; g_ssy[b] = e2; g_dxy[b] = d2; }
        }
    }

    // ---- Two-level last-block election (max 8 serialized atomics/counter) ----
    __shared__ bool isLast;
    __syncthreads();                 // CTA-order all global stores
    if (t == 0) {
        __threadfence();             // cumulative release for the block
        bool last = false;
        unsigned r = atomicAdd(&g_grp[b & (NGRP - 1)].v, 1u);
        if (r == GRP_SZ - 1) {       // this group is complete
            unsigned r2 = atomicAdd(&g_super.v, 1u);
            last = (r2 == NGRP - 1);
        }
        isLast = last;
    }
    __syncthreads();
    if (!isLast) return;
    if (t == 0) __threadfence();     // cumulative acquire
    __syncthreads();

    // ---- Phase 2: finalize (last block, 256 threads) ----
    // Colsum partials: thread (sl, cg) folds 16 blocks (4 parallel chains).
    const int cg = t & 31;
    const int sl = t >> 5;           // 0..7, covers blocks 16sl..16sl+15
    {
        float4 a0 = z, a1 = z, a2 = z, a3 = z;
        float4 b0 = z, b1 = z, b2 = z, b3 = z;
        const int base = sl * 16;
        #pragma unroll
        for (int k = 0; k < 4; k++) {
            a0 = f4add(a0, ldcg4(&g_csx4[(base + 4 * k)     * 32 + cg]));
            a1 = f4add(a1, ldcg4(&g_csx4[(base + 4 * k + 1) * 32 + cg]));
            a2 = f4add(a2, ldcg4(&g_csx4[(base + 4 * k + 2) * 32 + cg]));
            a3 = f4add(a3, ldcg4(&g_csx4[(base + 4 * k + 3) * 32 + cg]));
            b0 = f4add(b0, ldcg4(&g_csy4[(base + 4 * k)     * 32 + cg]));
            b1 = f4add(b1, ldcg4(&g_csy4[(base + 4 * k + 1) * 32 + cg]));
            b2 = f4add(b2, ldcg4(&g_csy4[(base + 4 * k + 2) * 32 + cg]));
            b3 = f4add(b3, ldcg4(&g_csy4[(base + 4 * k + 3) * 32 + cg]));
        }
        shx[sl * 32 + cg] = f4add(f4add(a0, a1), f4add(a2, a3));
        shy[sl * 32 + cg] = f4add(f4add(b0, b1), f4add(b2, b3));
    }
    __syncthreads();

    __shared__ double sP;
    __shared__ double sc[3];
    if (t < 32) {
        // Full colsums for column group t, then P partial in double.
        float4 ax = shx[t], ay = shy[t];
        #pragma unroll
        for (int k = 1; k < NWARP; k++) {
            ax = f4add(ax, shx[k * 32 + t]);
            ay = f4add(ay, shy[k * 32 + t]);
        }
        double p = (double)ax.x * (double)ay.x + (double)ax.y * (double)ay.y
                 + (double)ax.z * (double)ay.z + (double)ax.w * (double)ay.w;
        #pragma unroll
        for (int o = 16; o; o >>= 1)
            p += __shfl_down_sync(0xffffffffu, p, o);
        if (lane == 0) sP = p;
    } else if (t < 128) {
        // Warps 1..3: reduce the three 128-entry scalar arrays (fixed order).
        const int w = s - 1;         // 0..2
        const float* src = (w == 0) ? g_ssx : (w == 1) ? g_ssy : g_dxy;
        double acc = ((double)src[lane]      + (double)src[lane + 32])
                   + ((double)src[lane + 64] + (double)src[lane + 96]);
        #pragma unroll
        for (int o = 16; o; o >>= 1)
            acc += __shfl_down_sync(0xffffffffu, acc, o);
        if (lane == 0) sc[w] = acc;
    }
    __syncthreads();

    if (t == 0) {
        double Nn   = (double)N;
        double loss = (Nn - 1.0) * (sc[0] + sc[1]) - 2.0 * sP + 2.0 * sc[2];
        out[0] = (float)(loss / (2.0 * Nn * (Nn - 1.0)));
    }
    // Reset counters for the next graph replay (parallel, all done here).
    if (t >= 128 && t < 128 + NGRP) g_grp[t - 128].v = 0;
    if (t == 160) g_super.v = 0;
}

extern "C" void kernel_launch(void* const* d_in, const int* in_sizes, int n_in,
                              void* d_out, int out_size)
{
    const float4* f1 = (const float4*)d_in[0];
    const float4* f2 = (const float4*)d_in[1];
    // d_in[2] = label (int64) — mathematically unused by the reference.

    const int N      = in_sizes[0] / DCOLS;   // 8192
    const int total4 = in_sizes[0] / 4;       // float4 count per tensor

    cl_fused_kernel<<<NBLK, NTHR>>>(f1, f2, total4, N, (float*)d_out);
}